// round 6
// baseline (speedup 1.0000x reference)
#include <cuda_runtime.h>
#include <cstdint>

#define NN 1024
#define T 16
#define B 64
#define EPS 1e-9
#define NBLK 148
#define NTHR 256
#define GSZ (NBLK * NTHR)

// ---- scratch (device globals) ----
__device__ double g_dp[NN * NN];                 // dp[i][j], row-major
__device__ double g_S[NN * NN];                  // premasked scores, f64
__device__ float  g_c[NN * NN];                  // premasked scores, f32
__device__ unsigned long long g_far[15 * B * B]; // far-split accum per tile slot
__device__ int g_base[NN];
__device__ unsigned g_bar_arrive;
__device__ unsigned g_bar_gen;

__device__ __forceinline__ unsigned long long umaxll(unsigned long long a, unsigned long long b) {
    return a > b ? a : b;
}
__device__ __forceinline__ unsigned long long dbits(double x) {
    return (unsigned long long)__double_as_longlong(x);
}

// ---------------- base indices + barrier init ----------------
__global__ void k_base(const float* __restrict__ feat) {
    int i = blockIdx.x * blockDim.x + threadIdx.x;
    if (i == 0) { g_bar_arrive = 0u; g_bar_gen = 0u; }
    if (i < NN) {
        float best = feat[(size_t)i * NN];
        int bi = 0;
        #pragma unroll
        for (int ch = 1; ch < 4; ch++) {
            float v = feat[(size_t)ch * NN * NN + (size_t)i * NN];
            if (v > best) { best = v; bi = ch; }
        }
        g_base[i] = bi;
    }
}

// ---------------- premask + zero output ----------------
__global__ void k_premask(const float* __restrict__ con, float* __restrict__ out) {
    int j = blockIdx.x * blockDim.x + threadIdx.x;
    int i = blockIdx.y;
    const int pr[4] = {2, 3, 5, 7};
    float c = 0.5f * (con[(size_t)i * NN + j] + con[(size_t)j * NN + i]);
    int dd = i - j; if (dd < 0) dd = -dd;
    int prod = pr[g_base[i]] * pr[g_base[j]];
    bool ok = (dd >= 4) && (prod == 14 || prod == 15 || prod == 35);
    float cv = ok ? c : 0.0f;
    g_c[i * NN + j] = cv;
    g_S[i * NN + j] = (double)cv;
    out[i * NN + j] = 0.0f;
}

// ---------------- grid-wide barrier ----------------
__device__ __forceinline__ void gridbar(unsigned& lgen) {
    __syncthreads();
    if (threadIdx.x == 0) {
        __threadfence();
        unsigned target = lgen + 1;
        if (atomicAdd(&g_bar_arrive, 1u) == NBLK - 1) {
            atomicExch(&g_bar_arrive, 0u);
            __threadfence();
            atomicAdd(&g_bar_gen, 1u);
        } else {
            while (*(volatile unsigned*)&g_bar_gen < target) __nanosleep(64);
        }
        __threadfence();
    }
    __syncthreads();
    lgen++;
}

// ---------------- diagonal tile (I,I): triangular DP in smem ----------------
__device__ void diag_tile(int I, double* sbuf) {
    const int tid = threadIdx.x;
    for (int idx = tid; idx < B * 65; idx += NTHR) sbuf[idx] = 0.0;
    __syncthreads();
    const int IB = I * B;
    for (int u = 1; u < B; u++) {
        int c = tid >> 2, sub = tid & 3;
        int li = c, lj = c + u;
        bool active = (lj < B);
        unsigned long long acc = 0ULL;
        if (active) {
            for (int q = sub; q < u; q += 4) {       // r' = li+1 .. lj
                int rp = li + 1 + q;
                double cand = sbuf[li * 65 + (rp - 1)] + sbuf[rp * 65 + lj];
                acc = umaxll(acc, dbits(cand));
            }
        }
        acc = umaxll(acc, __shfl_xor_sync(0xffffffffu, acc, 1));
        acc = umaxll(acc, __shfl_xor_sync(0xffffffffu, acc, 2));
        if (active && sub == 0) {
            int i = IB + li, j = IB + lj;
            double pairv = sbuf[(li + 1) * 65 + (lj - 1)] + g_S[i * NN + j];
            acc = umaxll(acc, dbits(pairv));
            double v = __longlong_as_double((long long)acc);
            sbuf[li * 65 + lj] = v;
            g_dp[i * NN + j] = v;
        }
        __syncthreads();
    }
}

// ---------------- max-plus GEMM unit: far contributions ----------------
// far[i][j] = max over r in [rbase, rbase+32) of dp[i][r-1] + dp[r][j]
__device__ void gemm_unit(int I, int J, int chunk, double* sbuf) {
    double* As = sbuf;            // [64][33]
    double* Bs = sbuf + 64 * 33;  // [32][65]
    const int tid = threadIdx.x;
    const int IB = I * B, JB = J * B;
    const int rbase = (I + 1) * B + chunk * 32;
    __syncthreads();
    for (int idx = tid; idx < 64 * 32; idx += NTHR) {
        int li = idx >> 5, rr = idx & 31;
        As[li * 33 + rr] = g_dp[(IB + li) * NN + (rbase - 1 + rr)];
    }
    for (int idx = tid; idx < 32 * 64; idx += NTHR) {
        int rr = idx >> 6, lj = idx & 63;
        Bs[rr * 65 + lj] = g_dp[(rbase + rr) * NN + JB + lj];
    }
    __syncthreads();
    const int ty = tid >> 4, tx = tid & 15;
    unsigned long long acc[4][4];
    #pragma unroll
    for (int q = 0; q < 4; q++)
        #pragma unroll
        for (int p = 0; p < 4; p++) acc[q][p] = 0ULL;
    #pragma unroll 4
    for (int rr = 0; rr < 32; rr++) {
        double a[4], b[4];
        #pragma unroll
        for (int q = 0; q < 4; q++) a[q] = As[(ty * 4 + q) * 33 + rr];
        #pragma unroll
        for (int p = 0; p < 4; p++) b[p] = Bs[rr * 65 + tx * 4 + p];
        #pragma unroll
        for (int q = 0; q < 4; q++)
            #pragma unroll
            for (int p = 0; p < 4; p++)
                acc[q][p] = umaxll(acc[q][p], dbits(a[q] + b[p]));
    }
    unsigned long long* far = &g_far[I * B * B];
    #pragma unroll
    for (int q = 0; q < 4; q++)
        #pragma unroll
        for (int p = 0; p < 4; p++)
            atomicMax(&far[(ty * 4 + q) * 64 + tx * 4 + p], acc[q][p]);
}

// ---------------- off-diagonal tile wavefront ----------------
__device__ void wave_tile(int I, int td, double* sbuf) {
    const int J = I + td;
    const int tid = threadIdx.x;
    const int IB = I * B, JB = J * B;
    double* tile = sbuf;  // [64][65]
    unsigned long long* far = &g_far[I * B * B];
    for (int u = 0; u < 2 * B - 1; u++) {
        int lo = u > 63 ? u - 63 : 0;
        int hi = u < 63 ? u : 63;
        int cnt = hi - lo + 1;
        int c = tid >> 2, sub = tid & 3;
        int lj = lo + c;
        int li = 63 - u + lj;
        bool active = (c < cnt);
        unsigned long long acc = 0ULL;
        if (active) {
            int i = IB + li, j = JB + lj;
            int rowI = i * NN + IB;
            int leftLen = 63 - li;
            int L = u + 1;
            for (int q = sub; q < L; q += 4) {
                double cand;
                if (q < leftLen) {                   // r in tile I
                    int rp = li + 1 + q;
                    cand = g_dp[rowI + rp - 1] + tile[rp * 65 + lj];
                } else {                             // r in tile J
                    int rpp = q - leftLen;           // 0..lj
                    double lv = (rpp == 0) ? g_dp[i * NN + JB - 1]
                                           : tile[li * 65 + rpp - 1];
                    cand = lv + g_dp[(JB + rpp) * NN + j];
                }
                acc = umaxll(acc, dbits(cand));
            }
        }
        acc = umaxll(acc, __shfl_xor_sync(0xffffffffu, acc, 1));
        acc = umaxll(acc, __shfl_xor_sync(0xffffffffu, acc, 2));
        if (active && sub == 0) {
            int i = IB + li, j = JB + lj;
            acc = umaxll(acc, far[li * 64 + lj]);
            double pairv = g_dp[(i + 1) * NN + (j - 1)] + g_S[i * NN + j];
            acc = umaxll(acc, dbits(pairv));
            double v = __longlong_as_double((long long)acc);
            tile[li * 65 + lj] = v;
            g_dp[i * NN + j] = v;
        }
        __syncthreads();
    }
    for (int idx = tid; idx < B * B; idx += NTHR) far[idx] = 0ULL; // reset slot
}

// ---------------- persistent blocked DP ----------------
__global__ void __launch_bounds__(NTHR, 1) k_dp() {
    __shared__ double sbuf[4224];  // GEMM: 64x33 + 32x65; wave: 64x65
    const int gtid = blockIdx.x * NTHR + threadIdx.x;
    unsigned lgen = 0;

    for (int idx = gtid; idx < NN * NN; idx += GSZ) g_dp[idx] = 0.0;
    for (int idx = gtid; idx < 15 * B * B; idx += GSZ) g_far[idx] = 0ULL;
    gridbar(lgen);

    if (blockIdx.x < T) diag_tile(blockIdx.x, sbuf);
    gridbar(lgen);

    for (int td = 1; td < T; td++) {
        const int nt = T - td;
        if (td >= 2) {
            const int nchunks = (td - 1) * 2;
            const int units = nt * nchunks;
            for (int u = blockIdx.x; u < units; u += NBLK) {
                int I = u % nt;
                int chunk = u / nt;
                gemm_unit(I, I + td, chunk, sbuf);
            }
        }
        gridbar(lgen);
        if (blockIdx.x < nt) wave_tile(blockIdx.x, td, sbuf);
        gridbar(lgen);
    }
}

// ---------------- traceback (single CTA, batched loads) ----------------
__global__ void k_traceback(float* __restrict__ out) {
    const int tid = threadIdx.x;  // 256 threads
    const int lane = tid & 31, wid = tid >> 5;
    __shared__ int2 stk[2048];
    __shared__ int sp_s, cmd, ci, cj, rk;
    __shared__ double wv[8];
    __shared__ int wi[8];

    if (tid == 0) { stk[0] = make_int2(0, NN - 1); sp_s = 1; }
    __syncthreads();

    long long steps = 0;
    while (true) {
        if (tid == 0) {
            cmd = 0;
            while (sp_s > 0) {
                if (++steps > 2000000LL) { cmd = 0; sp_s = 0; break; }
                int2 e = stk[--sp_s];
                int i = e.x, j = e.y;
                if (j <= i) continue;
                // batch-issue all four loads (independent -> one latency round)
                double v     = g_dp[i * NN + j];
                double up    = g_dp[(i + 1) * NN + j];
                double inner = g_dp[(i + 1) * NN + (j - 1)];
                double s     = g_S[i * NN + j];
                if (v <= EPS) continue;
                if (up >= v - EPS) { stk[sp_s++] = make_int2(i + 1, j); continue; }
                if (s > 0.0 && inner + s >= v - EPS) {
                    out[i * NN + j] = g_c[i * NN + j];
                    out[j * NN + i] = g_c[j * NN + i];
                    stk[sp_s++] = make_int2(i + 1, j - 1);
                    continue;
                }
                cmd = 1; ci = i; cj = j;
                break;
            }
        }
        __syncthreads();
        if (cmd == 0) break;

        int i = ci, j = cj;
        double bestv = -1.0;
        int bestk = NN + 1;
        for (int k = i + tid; k < j; k += 256) {  // ascending: strict > keeps first
            double v = g_dp[i * NN + k] + g_dp[(k + 1) * NN + j];
            if (v > bestv) { bestv = v; bestk = k; }
        }
        #pragma unroll
        for (int off = 16; off > 0; off >>= 1) {
            double ov = __shfl_down_sync(0xffffffffu, bestv, off);
            int    oi = __shfl_down_sync(0xffffffffu, bestk, off);
            if (ov > bestv || (ov == bestv && oi < bestk)) { bestv = ov; bestk = oi; }
        }
        if (lane == 0) { wv[wid] = bestv; wi[wid] = bestk; }
        __syncthreads();
        if (tid == 0) {
            double bv = wv[0]; int bk = wi[0];
            #pragma unroll
            for (int w = 1; w < 8; w++) {
                if (wv[w] > bv || (wv[w] == bv && wi[w] < bk)) { bv = wv[w]; bk = wi[w]; }
            }
            rk = bk;
        }
        __syncthreads();
        if (tid == 0) {
            int k = rk;
            stk[sp_s++] = make_int2(i, k);
            stk[sp_s++] = make_int2(k + 1, j);
        }
        __syncthreads();
    }
}

// ---------------- launch (4 graph nodes) ----------------
extern "C" void kernel_launch(void* const* d_in, const int* in_sizes, int n_in,
                              void* d_out, int out_size) {
    const float* con  = (const float*)d_in[0];
    const float* feat = (const float*)d_in[1];
    float* out = (float*)d_out;

    k_base<<<(NN + 255) / 256, 256>>>(feat);
    k_premask<<<dim3(NN / 256, NN), 256>>>(con, out);
    k_dp<<<NBLK, NTHR>>>();
    k_traceback<<<1, 256>>>(out);
}

// round 8
// speedup vs baseline: 1.6891x; 1.6891x over previous
#include <cuda_runtime.h>
#include <cstdint>

#define NN 1024
#define T 16
#define B 64
#define EPS 1e-9
#define NBLK 148
#define NTHR 512
#define GSZ (NBLK * NTHR)

typedef unsigned long long ull;

// ---- scratch (device globals) ----
__device__ double g_dp[NN * NN];                 // dp[i][j], row-major
__device__ double g_S[NN * NN];                  // premasked scores, f64
__device__ float  g_c[NN * NN];                  // premasked scores, f32
__device__ ull    g_far[15 * B * B];             // far-split accum per tile slot
__device__ int g_base[NN];
__device__ unsigned g_bar_arrive;
__device__ unsigned g_bar_gen;

__device__ __forceinline__ ull umaxll(ull a, ull b) { return a > b ? a : b; }
__device__ __forceinline__ ull dbits(double x) { return (ull)__double_as_longlong(x); }

// dynamic smem layout (doubles)
#define OFF_CUR 0
#define OFF_DI  4160
#define OFF_DJ  8320
#define OFF_ST  12480
#define OFF_C1  16640   /* 65: dp[IB+t][JB-1], t=0..64 */
#define OFF_R64 16705   /* 64: dp[IB+64][JB-1+t], t=0..63 */
#define SMEM_DBL 16769
#define SMEM_BYTES (SMEM_DBL * 8)

// ---------------- base indices + barrier init ----------------
__global__ void k_base(const float* __restrict__ feat) {
    int i = blockIdx.x * blockDim.x + threadIdx.x;
    if (i == 0) { g_bar_arrive = 0u; g_bar_gen = 0u; }
    if (i < NN) {
        float best = feat[(size_t)i * NN];
        int bi = 0;
        #pragma unroll
        for (int ch = 1; ch < 4; ch++) {
            float v = feat[(size_t)ch * NN * NN + (size_t)i * NN];
            if (v > best) { best = v; bi = ch; }
        }
        g_base[i] = bi;
    }
}

// ---------------- premask + zero output ----------------
__global__ void k_premask(const float* __restrict__ con, float* __restrict__ out) {
    int j = blockIdx.x * blockDim.x + threadIdx.x;
    int i = blockIdx.y;
    const int pr[4] = {2, 3, 5, 7};
    float c = 0.5f * (con[(size_t)i * NN + j] + con[(size_t)j * NN + i]);
    int dd = i - j; if (dd < 0) dd = -dd;
    int prod = pr[g_base[i]] * pr[g_base[j]];
    bool ok = (dd >= 4) && (prod == 14 || prod == 15 || prod == 35);
    float cv = ok ? c : 0.0f;
    g_c[i * NN + j] = cv;
    g_S[i * NN + j] = (double)cv;
    out[i * NN + j] = 0.0f;
}

// ---------------- grid-wide barrier ----------------
__device__ __forceinline__ void gridbar(unsigned& lgen) {
    __syncthreads();
    if (threadIdx.x == 0) {
        __threadfence();
        unsigned target = lgen + 1;
        if (atomicAdd(&g_bar_arrive, 1u) == NBLK - 1) {
            atomicExch(&g_bar_arrive, 0u);
            __threadfence();
            atomicAdd(&g_bar_gen, 1u);
        } else {
            while (*(volatile unsigned*)&g_bar_gen < target) __nanosleep(64);
        }
        __threadfence();
    }
    __syncthreads();
    lgen++;
}

// ---------------- diagonal tile (I,I): triangular DP in smem ----------------
__device__ void diag_tile(int I, double* sbuf) {
    const int tid = threadIdx.x;
    for (int idx = tid; idx < B * 65; idx += NTHR) sbuf[idx] = 0.0;
    __syncthreads();
    const int IB = I * B;
    for (int u = 1; u < B; u++) {
        int c = tid >> 3, sub = tid & 7;
        int li = c, lj = c + u;
        bool active = (lj < B);
        ull acc = 0ULL;
        if (active) {
            for (int q = sub; q < u; q += 8) {
                int rp = li + 1 + q;
                acc = umaxll(acc, dbits(sbuf[li * 65 + (rp - 1)] + sbuf[rp * 65 + lj]));
            }
        }
        acc = umaxll(acc, __shfl_xor_sync(0xffffffffu, acc, 1));
        acc = umaxll(acc, __shfl_xor_sync(0xffffffffu, acc, 2));
        acc = umaxll(acc, __shfl_xor_sync(0xffffffffu, acc, 4));
        if (active && sub == 0) {
            int i = IB + li, j = IB + lj;
            acc = umaxll(acc, dbits(sbuf[(li + 1) * 65 + (lj - 1)] + g_S[i * NN + j]));
            double v = __longlong_as_double((long long)acc);
            sbuf[li * 65 + lj] = v;
            g_dp[i * NN + j] = v;
        }
        __syncthreads();
    }
}

// ---------------- max-plus GEMM unit ----------------
// far[i][j] = max over r in [rbase, rbase+32) of dp[i][r-1] + dp[r][j]
__device__ void gemm_unit(int I, int J, int chunk, double* sbuf) {
    double* As = sbuf;            // [64][33]
    double* Bs = sbuf + 64 * 33;  // [32][65]
    const int tid = threadIdx.x;
    const int IB = I * B, JB = J * B;
    const int rbase = (I + 1) * B + chunk * 32;
    __syncthreads();
    for (int idx = tid; idx < 64 * 32; idx += NTHR) {
        int li = idx >> 5, rr = idx & 31;
        As[li * 33 + rr] = g_dp[(IB + li) * NN + (rbase - 1 + rr)];
    }
    for (int idx = tid; idx < 32 * 64; idx += NTHR) {
        int rr = idx >> 6, lj = idx & 63;
        Bs[rr * 65 + lj] = g_dp[(rbase + rr) * NN + JB + lj];
    }
    __syncthreads();
    const int ty = tid >> 4, tx = tid & 15;   // 32 row-groups x 16 col-groups
    ull acc[2][4];
    #pragma unroll
    for (int q = 0; q < 2; q++)
        #pragma unroll
        for (int p = 0; p < 4; p++) acc[q][p] = 0ULL;
    #pragma unroll 4
    for (int rr = 0; rr < 32; rr++) {
        double a[2], b[4];
        #pragma unroll
        for (int q = 0; q < 2; q++) a[q] = As[(ty * 2 + q) * 33 + rr];
        #pragma unroll
        for (int p = 0; p < 4; p++) b[p] = Bs[rr * 65 + tx * 4 + p];
        #pragma unroll
        for (int q = 0; q < 2; q++)
            #pragma unroll
            for (int p = 0; p < 4; p++)
                acc[q][p] = umaxll(acc[q][p], dbits(a[q] + b[p]));
    }
    ull* far = &g_far[I * B * B];
    #pragma unroll
    for (int q = 0; q < 2; q++)
        #pragma unroll
        for (int p = 0; p < 4; p++)
            atomicMax(&far[(ty * 2 + q) * 64 + tx * 4 + p], acc[q][p]);
}

// ---------------- off-diagonal tile wavefront (all-smem) ----------------
__device__ void wave_tile(int I, int td, double* sm) {
    double* cur   = sm + OFF_CUR;
    double* dI    = sm + OFF_DI;
    double* dJ    = sm + OFF_DJ;
    double* St    = sm + OFF_ST;
    double* colm1 = sm + OFF_C1;
    double* row64 = sm + OFF_R64;
    const int J = I + td;
    const int tid = threadIdx.x;
    const int IB = I * B, JB = J * B;

    // preload all inputs to smem
    for (int idx = tid; idx < 64 * 64; idx += NTHR) {
        int r = idx >> 6, c = idx & 63;
        dI[r * 65 + c] = g_dp[(IB + r) * NN + IB + c];
        dJ[r * 65 + c] = g_dp[(JB + r) * NN + JB + c];
        St[r * 65 + c] = g_S[(IB + r) * NN + JB + c];
    }
    for (int t = tid; t < 65; t += NTHR) colm1[t] = g_dp[(IB + t) * NN + (JB - 1)];
    for (int t = tid; t < 64; t += NTHR) row64[t] = g_dp[(IB + 64) * NN + (JB - 1 + t)];
    __syncthreads();

    ull* far = &g_far[I * B * B];
    for (int u = 0; u < 2 * B - 1; u++) {
        int lo = u > 63 ? u - 63 : 0;
        int hi = u < 63 ? u : 63;
        int c = tid >> 3, sub = tid & 7;
        int lj = lo + c;
        int li = 63 - u + lj;
        bool active = (lj <= hi);
        ull acc = 0ULL;
        if (active) {
            int L = u + 1;
            int leftLen = 63 - li;     // = u - lj
            for (int q = sub; q < L; q += 8) {
                double cand;
                if (q < leftLen) {                    // split r in tile I
                    int rp = li + 1 + q;
                    cand = dI[li * 65 + rp - 1] + cur[rp * 65 + lj];
                } else {                              // split r in tile J
                    int rpp = q - leftLen;            // 0..lj
                    double lv = (rpp == 0) ? colm1[li] : cur[li * 65 + rpp - 1];
                    cand = lv + dJ[rpp * 65 + lj];
                }
                acc = umaxll(acc, dbits(cand));
            }
        }
        acc = umaxll(acc, __shfl_xor_sync(0xffffffffu, acc, 1));
        acc = umaxll(acc, __shfl_xor_sync(0xffffffffu, acc, 2));
        acc = umaxll(acc, __shfl_xor_sync(0xffffffffu, acc, 4));
        if (active && sub == 0) {
            acc = umaxll(acc, far[li * 64 + lj]);
            double pl = (li < 63) ? ((lj > 0) ? cur[(li + 1) * 65 + (lj - 1)] : colm1[li + 1])
                                  : row64[lj];
            acc = umaxll(acc, dbits(pl + St[li * 65 + lj]));
            double v = __longlong_as_double((long long)acc);
            cur[li * 65 + lj] = v;
            g_dp[(IB + li) * NN + (JB + lj)] = v;
        }
        __syncthreads();
    }
    for (int idx = tid; idx < B * B; idx += NTHR) far[idx] = 0ULL; // reset slot
}

// ---------------- persistent blocked DP ----------------
__global__ void __launch_bounds__(NTHR, 1) k_dp() {
    extern __shared__ double sm[];
    const int gtid = blockIdx.x * NTHR + threadIdx.x;
    unsigned lgen = 0;

    for (int idx = gtid; idx < NN * NN; idx += GSZ) g_dp[idx] = 0.0;
    for (int idx = gtid; idx < 15 * B * B; idx += GSZ) g_far[idx] = 0ULL;
    gridbar(lgen);

    if (blockIdx.x < T) diag_tile(blockIdx.x, sm);
    gridbar(lgen);

    for (int td = 1; td < T; td++) {
        const int nt = T - td;
        if (td >= 2) {
            const int nchunks = (td - 1) * 2;
            const int units = nt * nchunks;
            for (int u = blockIdx.x; u < units; u += NBLK) {
                int I = u % nt;
                int chunk = u / nt;
                gemm_unit(I, I + td, chunk, sm);
            }
        }
        gridbar(lgen);
        if (blockIdx.x < nt) wave_tile(blockIdx.x, td, sm);
        gridbar(lgen);
    }
}

// ---------------- warp-parallel traceback (1 CTA, 32 warps) ----------------
__global__ void __launch_bounds__(1024, 1) k_traceback(float* __restrict__ out) {
    const int tid = threadIdx.x;
    const int lane = tid & 31;
    __shared__ int2 stk[4096];
    __shared__ int top, pending, lock;
    if (tid == 0) { stk[0] = make_int2(0, NN - 1); top = 1; pending = 1; lock = 0; }
    __syncthreads();

    volatile int* vtop = &top;
    volatile int* vpend = &pending;

    int ci = 0, cj = 0;
    bool have = false;
    long long guard = 0;

    while (true) {
        if (++guard > 80000000LL) break;  // safety
        if (!have) {
            int got = 0, ex = 0, ei = 0, ej = 0;
            if (lane == 0) {
                if (atomicCAS(&lock, 0, 1) == 0) {
                    __threadfence_block();
                    int t = *vtop;
                    if (t > 0) { int2 e = stk[t - 1]; *vtop = t - 1; ei = e.x; ej = e.y; got = 1; }
                    __threadfence_block();
                    atomicExch(&lock, 0);
                }
                if (!got && *vpend == 0) ex = 1;
            }
            got = __shfl_sync(0xffffffffu, got, 0);
            ex  = __shfl_sync(0xffffffffu, ex, 0);
            if (got) {
                ci = __shfl_sync(0xffffffffu, ei, 0);
                cj = __shfl_sync(0xffffffffu, ej, 0);
                have = true;
            } else if (ex) {
                break;
            } else {
                __nanosleep(64);
                continue;
            }
        }

        int i = ci, j = cj;
        if (j <= i) { have = false; if (lane == 0) atomicSub(&pending, 1); __syncwarp(); continue; }
        double v = g_dp[i * NN + j];
        if (v <= EPS) { have = false; if (lane == 0) atomicSub(&pending, 1); __syncwarp(); continue; }
        double up    = g_dp[(i + 1) * NN + j];
        double inner = g_dp[(i + 1) * NN + (j - 1)];
        double s     = g_S[i * NN + j];
        if (up >= v - EPS) { ci = i + 1; continue; }
        if (s > 0.0 && inner + s >= v - EPS) {
            if (lane == 0) {
                out[i * NN + j] = g_c[i * NN + j];
                out[j * NN + i] = g_c[j * NN + i];
            }
            ci = i + 1; cj = j - 1;
            continue;
        }
        // split: warp argmax, first-max tie-break (== np.argmax)
        double bestv = -1.0;
        int bestk = NN + 1;
        for (int k = i + lane; k < j; k += 32) {
            double val = g_dp[i * NN + k] + g_dp[(k + 1) * NN + j];
            if (val > bestv) { bestv = val; bestk = k; }
        }
        #pragma unroll
        for (int off = 16; off > 0; off >>= 1) {
            double ov = __shfl_down_sync(0xffffffffu, bestv, off);
            int    oi = __shfl_down_sync(0xffffffffu, bestk, off);
            if (ov > bestv || (ov == bestv && oi < bestk)) { bestv = ov; bestk = oi; }
        }
        int k = __shfl_sync(0xffffffffu, bestk, 0);
        if (lane == 0) {
            atomicAdd(&pending, 1);
            while (atomicCAS(&lock, 0, 1) != 0) __nanosleep(32);
            __threadfence_block();
            int t = *vtop;
            stk[t] = make_int2(i, k);
            *vtop = t + 1;
            __threadfence_block();
            atomicExch(&lock, 0);
        }
        __syncwarp();
        ci = k + 1;  // continue with (k+1, j)
    }
}

// ---------------- launch (4 graph nodes) ----------------
extern "C" void kernel_launch(void* const* d_in, const int* in_sizes, int n_in,
                              void* d_out, int out_size) {
    const float* con  = (const float*)d_in[0];
    const float* feat = (const float*)d_in[1];
    float* out = (float*)d_out;

    static int smem_set = 0;
    if (!smem_set) {
        cudaFuncSetAttribute(k_dp, cudaFuncAttributeMaxDynamicSharedMemorySize, SMEM_BYTES);
        smem_set = 1;
    }

    k_base<<<(NN + 255) / 256, 256>>>(feat);
    k_premask<<<dim3(NN / 256, NN), 256>>>(con, out);
    k_dp<<<NBLK, NTHR, SMEM_BYTES>>>();
    k_traceback<<<1, 1024>>>(out);
}